// round 15
// baseline (speedup 1.0000x reference)
#include <cuda_runtime.h>
#include <cuda_fp16.h>
#include <cstdint>
#include <cstddef>

#define GN 50000
#define GE 1600000
#define GR 4
#define GD 128
#define NBINS (GR * GN)          // 200000 buckets (r, row)
#define CAP 80                   // bucket capacity; P(Poisson(32) >= 80) ~ 1e-13

#define FRONT_GEMM 1024          // gemm blocks in fused front kernel
#define FRONT_SCATX 512          // scatter x-blocks per r
#define FRONT_BLOCKS (FRONT_GEMM + FRONT_SCATX * GR)   // 3072

// Scratch: device globals (no allocations allowed).
// h, y in fp16; edge record packed to 4B {val:fp16 <<16 | col:u16}.
__device__ __align__(16) __half   g_h[(size_t)GN * GD];          // 12.8 MB
__device__ __align__(16) __half   g_y[(size_t)GR * GN * GD];     // 51.2 MB
__device__ __align__(16) unsigned g_edges[(size_t)NBINS * CAP];  // 64 MB (sparse-touched)
__device__ int g_count[NBINS];   // zero at first use (BSS); re-zeroed by k_pass2

__device__ __forceinline__ void fma2(uint64_t& acc, uint64_t a, uint64_t b) {
    asm("fma.rn.f32x2 %0, %1, %2, %0;" : "+l"(acc) : "l"(a), "l"(b));
}

__device__ __forceinline__ float2 unpack_f32x2(uint64_t p) {
    float2 f;
    asm("mov.b64 {%0, %1}, %2;" : "=f"(f.x), "=f"(f.y) : "l"(p));
    return f;
}

// ---------------------------------------------------------------------------
// Launch 1 (fused front): blocks [0, FRONT_GEMM) do h = x @ W (f32x2 math,
// fp16 store, 64KB smem W tile); remaining blocks do the bucket scatter.
// GEMM is FMA-pipe-bound, scatter is L2-atomic/sector-bound -> they overlap.
// ---------------------------------------------------------------------------
__global__ void k_front(const float* __restrict__ x, const float* __restrict__ w,
                        const int* __restrict__ rows, const int* __restrict__ cols,
                        const float* __restrict__ vals) {
    extern __shared__ float ws[];
    if (blockIdx.x < FRONT_GEMM) {
        for (int i = threadIdx.x; i < GD * GD / 4; i += blockDim.x)
            reinterpret_cast<float4*>(ws)[i] = reinterpret_cast<const float4*>(w)[i];
        __syncthreads();

        const int lane   = threadIdx.x & 31;
        const int warp   = (int)((blockIdx.x * blockDim.x + threadIdx.x) >> 5);
        const int nwarps = (FRONT_GEMM * 256) >> 5;
        const ulonglong2* ws2 = reinterpret_cast<const ulonglong2*>(ws);

        for (int row = warp; row < GN; row += nwarps) {
            float xr[4];
#pragma unroll
            for (int j = 0; j < 4; j++) xr[j] = x[(size_t)row * GD + j * 32 + lane];
            uint64_t a01 = 0ull, a23 = 0ull;
#pragma unroll
            for (int j = 0; j < 4; j++) {
#pragma unroll
                for (int kk = 0; kk < 32; kk++) {
                    const float xv = __shfl_sync(0xffffffffu, xr[j], kk);
                    uint64_t xv2;
                    asm("mov.b64 %0, {%1, %1};" : "=l"(xv2) : "f"(xv));
                    const ulonglong2 wv = ws2[(j * 32 + kk) * 32 + lane];
                    fma2(a01, wv.x, xv2);
                    fma2(a23, wv.y, xv2);
                }
            }
            const float2 f01 = unpack_f32x2(a01);
            const float2 f23 = unpack_f32x2(a23);
            const __half2 p = __floats2half2_rn(f01.x, f01.y);
            const __half2 q = __floats2half2_rn(f23.x, f23.y);
            uint2 o;
            o.x = *reinterpret_cast<const unsigned*>(&p);
            o.y = *reinterpret_cast<const unsigned*>(&q);
            reinterpret_cast<uint2*>(g_h)[(size_t)row * 32 + lane] = o;
        }
    } else {
        const int bx = blockIdx.x - FRONT_GEMM;
        const int r  = bx / FRONT_SCATX;
        const int b0 = bx - r * FRONT_SCATX;
        const int* __restrict__ rr = rows + (size_t)r * GE;
        const int* __restrict__ cc = cols + (size_t)r * GE;
        const float* __restrict__ vv = vals + (size_t)r * GE;

        for (int idx = b0 * blockDim.x + threadIdx.x; idx < GE;
             idx += FRONT_SCATX * 256) {
            const int b = r * GN + rr[idx];
            const int pos = atomicAdd(&g_count[b], 1);
            if (pos < CAP) {
                const unsigned short vh = __half_as_ushort(__float2half_rn(vv[idx]));
                g_edges[(size_t)b * CAP + pos] = (unsigned)cc[idx] | ((unsigned)vh << 16);
            }
        }
    }
}

// cvt fp16x2 -> f32x2, then fma.rn.f32x2 into a packed f32x2 accumulator.
__device__ __forceinline__ void cvt_fma(unsigned h2, uint64_t v2, uint64_t& acc) {
    asm("{\n\t"
        ".reg .b16 lo, hi;\n\t"
        ".reg .f32 flo, fhi;\n\t"
        ".reg .b64 g;\n\t"
        "mov.b32 {lo, hi}, %1;\n\t"
        "cvt.f32.f16 flo, lo;\n\t"
        "cvt.f32.f16 fhi, hi;\n\t"
        "mov.b64 g, {flo, fhi};\n\t"
        "fma.rn.f32x2 %0, g, %2, %0;\n\t"
        "}" : "+l"(acc) : "r"(h2), "l"(v2));
}

__device__ __forceinline__ uint64_t rec_v2(unsigned e) {
    float v;
    asm("{\n\t"
        ".reg .b16 lo, hi;\n\t"
        "mov.b32 {lo, hi}, %1;\n\t"
        "cvt.f32.f16 %0, hi;\n\t"
        "}" : "=f"(v) : "r"(e));
    uint64_t v2;
    asm("mov.b64 %0, {%1, %1};" : "=l"(v2) : "f"(v));
    return v2;
}

// ---------------------------------------------------------------------------
// Gather core, 16-edge batches (8 LDG.128 in flight per lane).  pk0 is the
// prefetched first-chunk edge word.  hi = lane>>4 edge parity; q = lane&15.
// ---------------------------------------------------------------------------
__device__ __forceinline__ void seg_core(const uint4* __restrict__ src,
                                         const unsigned* __restrict__ ebase,
                                         int cnt, int hi, int q,
                                         uint64_t acc[4], unsigned pk0) {
    unsigned pk = pk0;
    for (int i = 0; i < cnt; i += 32) {
        const int c = min(32, cnt - i);
        if (i > 0)
            pk = ((threadIdx.x & 31) < c) ? ebase[i + (threadIdx.x & 31)] : 0u;
        int t = 0;
        for (; t + 16 <= c; t += 16) {
            unsigned e[8];
#pragma unroll
            for (int j = 0; j < 8; j++)
                e[j] = __shfl_sync(0xffffffffu, pk, t + 2 * j + hi);
            uint4 g[8];
#pragma unroll
            for (int j = 0; j < 8; j++)
                g[j] = src[(size_t)(e[j] & 0xFFFFu) * 16 + q];
#pragma unroll
            for (int j = 0; j < 8; j++) {
                const uint64_t v = rec_v2(e[j]);
                cvt_fma(g[j].x, v, acc[0]); cvt_fma(g[j].y, v, acc[1]);
                cvt_fma(g[j].z, v, acc[2]); cvt_fma(g[j].w, v, acc[3]);
            }
        }
        for (; t + 8 <= c; t += 8) {
            unsigned e[4];
#pragma unroll
            for (int j = 0; j < 4; j++)
                e[j] = __shfl_sync(0xffffffffu, pk, t + 2 * j + hi);
            uint4 g[4];
#pragma unroll
            for (int j = 0; j < 4; j++)
                g[j] = src[(size_t)(e[j] & 0xFFFFu) * 16 + q];
#pragma unroll
            for (int j = 0; j < 4; j++) {
                const uint64_t v = rec_v2(e[j]);
                cvt_fma(g[j].x, v, acc[0]); cvt_fma(g[j].y, v, acc[1]);
                cvt_fma(g[j].z, v, acc[2]); cvt_fma(g[j].w, v, acc[3]);
            }
        }
        for (; t < c; t += 2) {
            // odd tail: hi=1 half-warp reads a zeroed shfl source -> v=0 no-op
            const unsigned e0 = __shfl_sync(0xffffffffu, pk, t + hi);
            const uint4 g0 = src[(size_t)(e0 & 0xFFFFu) * 16 + q];
            const uint64_t v0 = rec_v2(e0);
            cvt_fma(g0.x, v0, acc[0]); cvt_fma(g0.y, v0, acc[1]);
            cvt_fma(g0.z, v0, acc[2]); cvt_fma(g0.w, v0, acc[3]);
        }
    }
}

__device__ __forceinline__ void half_combine(uint64_t acc[4]) {
#pragma unroll
    for (int k = 0; k < 4; k++) {
        const uint64_t other = __shfl_xor_sync(0xffffffffu, acc[k], 16);
        asm("add.rn.f32x2 %0, %0, %1;" : "+l"(acc[k]) : "l"(other));
    }
}

// ---------------------------------------------------------------------------
// Launch 2: pass 1 (all r): y[b] = filt[b] * sum v * h[col].  Warp per bucket.
// ---------------------------------------------------------------------------
__global__ __launch_bounds__(256) void k_pass1(const float* __restrict__ filt) {
    const int lane = threadIdx.x & 31;
    const int hi   = lane >> 4;
    const int q    = lane & 15;
    const int b    = (blockIdx.x * blockDim.x + threadIdx.x) >> 5;   // NBINS % 8 == 0

    const int cnt = min(g_count[b], CAP);
    const unsigned pk0 = (lane < min(cnt, 32)) ? g_edges[(size_t)b * CAP + lane] : 0u;

    uint64_t acc[4] = {0ull, 0ull, 0ull, 0ull};
    seg_core(reinterpret_cast<const uint4*>(g_h), g_edges + (size_t)b * CAP,
             cnt, hi, q, acc, pk0);
    half_combine(acc);

    if (hi == 0) {
        const float f = __ldg(&filt[b]);
        const float2 a0 = unpack_f32x2(acc[0]);
        const float2 a1 = unpack_f32x2(acc[1]);
        const float2 a2 = unpack_f32x2(acc[2]);
        const float2 a3 = unpack_f32x2(acc[3]);
        const __half2 p0 = __floats2half2_rn(f * a0.x, f * a0.y);
        const __half2 p1 = __floats2half2_rn(f * a1.x, f * a1.y);
        const __half2 p2 = __floats2half2_rn(f * a2.x, f * a2.y);
        const __half2 p3 = __floats2half2_rn(f * a3.x, f * a3.y);
        uint4 o;
        o.x = *reinterpret_cast<const unsigned*>(&p0);
        o.y = *reinterpret_cast<const unsigned*>(&p1);
        o.z = *reinterpret_cast<const unsigned*>(&p2);
        o.w = *reinterpret_cast<const unsigned*>(&p3);
        reinterpret_cast<uint4*>(g_y)[(size_t)b * 16 + q] = o;
    }
}

// ---------------------------------------------------------------------------
// Launch 3: pass 2, row-per-warp, all 4 segment descriptors prefetched.
// out[row] = bias + sum_r sum v * y[r][col]; single store; re-zeroes counts.
// ---------------------------------------------------------------------------
__global__ __launch_bounds__(256) void k_pass2(const float* __restrict__ bias,
                                               float* __restrict__ out) {
    const int lane = threadIdx.x & 31;
    const int hi   = lane >> 4;
    const int q    = lane & 15;
    const int row  = (blockIdx.x * blockDim.x + threadIdx.x) >> 5;
    if (row >= GN) return;

    int cnt[GR];
#pragma unroll
    for (int r = 0; r < GR; r++) cnt[r] = min(g_count[r * GN + row], CAP);
    unsigned pk0[GR];
#pragma unroll
    for (int r = 0; r < GR; r++) {
        const size_t eb = (size_t)(r * GN + row) * CAP;
        pk0[r] = (lane < min(cnt[r], 32)) ? g_edges[eb + lane] : 0u;
    }
    if (lane == 0) {
#pragma unroll
        for (int r = 0; r < GR; r++) g_count[r * GN + row] = 0;
    }

    uint64_t acc[4] = {0ull, 0ull, 0ull, 0ull};
#pragma unroll
    for (int r = 0; r < GR; r++) {
        const size_t eb = (size_t)(r * GN + row) * CAP;
        const uint4* y4 = reinterpret_cast<const uint4*>(g_y) + (size_t)r * GN * 16;
        seg_core(y4, g_edges + eb, cnt[r], hi, q, acc, pk0[r]);
    }
    half_combine(acc);

    if (hi == 0) {
        const float2 a0 = unpack_f32x2(acc[0]);
        const float2 a1 = unpack_f32x2(acc[1]);
        const float2 a2 = unpack_f32x2(acc[2]);
        const float2 a3 = unpack_f32x2(acc[3]);
        const float4 b0 = reinterpret_cast<const float4*>(bias)[q * 2];
        const float4 b1 = reinterpret_cast<const float4*>(bias)[q * 2 + 1];
        float4* dst = reinterpret_cast<float4*>(out + (size_t)row * GD + q * 8);
        dst[0] = make_float4(a0.x + b0.x, a0.y + b0.y, a1.x + b0.z, a1.y + b0.w);
        dst[1] = make_float4(a2.x + b1.x, a2.y + b1.y, a3.x + b1.z, a3.y + b1.w);
    }
}

// ---------------------------------------------------------------------------
// Launch. Inputs (metadata order): x, vals, weight, filt, bias, rows, cols.
// ---------------------------------------------------------------------------
extern "C" void kernel_launch(void* const* d_in, const int* in_sizes, int n_in,
                              void* d_out, int out_size) {
    const float* x    = (const float*)d_in[0];
    const float* vals = (const float*)d_in[1];
    const float* w    = (const float*)d_in[2];
    const float* filt = (const float*)d_in[3];
    const float* bias = (const float*)d_in[4];
    const int*   rows = (const int*)d_in[5];
    const int*   cols = (const int*)d_in[6];
    float* out = (float*)d_out;
    (void)in_sizes; (void)n_in; (void)out_size;

    cudaFuncSetAttribute(k_front, cudaFuncAttributeMaxDynamicSharedMemorySize,
                         GD * GD * (int)sizeof(float));

    // 1) fused front: gemm (f32x2) + bucket scatter (overlapping pipes)
    k_front<<<FRONT_BLOCKS, 256, GD * GD * sizeof(float)>>>(x, w, rows, cols, vals);

    // 2) pass 1
    k_pass1<<<NBINS / 8, 256>>>(filt);

    // 3) pass 2 (+ count re-zero for next replay)
    k_pass2<<<(GN * 32 + 255) / 256, 256>>>(bias, out);
}

// round 16
// speedup vs baseline: 1.0262x; 1.0262x over previous
#include <cuda_runtime.h>
#include <cuda_fp16.h>
#include <cstdint>
#include <cstddef>

#define GN 50000
#define GE 1600000
#define GR 4
#define GD 128
#define NBINS (GR * GN)          // 200000 buckets (r, row)
#define CAP 80                   // bucket capacity; P(Poisson(32) >= 80) ~ 1e-13

#define GEMM_BLOCKS 1024
#define SCAT_BLOCKS_X 512        // x-dim; gridDim.y = GR

// Scratch: device globals (no allocations allowed).
// h, y in fp16; edge record packed to 4B {val:fp16 <<16 | col:u16}.
__device__ __align__(16) __half   g_h[(size_t)GN * GD];          // 12.8 MB
__device__ __align__(16) __half   g_y[(size_t)GR * GN * GD];     // 51.2 MB
__device__ __align__(16) unsigned g_edges[(size_t)NBINS * CAP];  // 64 MB (sparse-touched)
__device__ int g_count[NBINS];   // zero at first use (BSS); re-zeroed by k_pass2

__device__ __forceinline__ void fma2(uint64_t& acc, uint64_t a, uint64_t b) {
    asm("fma.rn.f32x2 %0, %1, %2, %0;" : "+l"(acc) : "l"(a), "l"(b));
}

__device__ __forceinline__ float2 unpack_f32x2(uint64_t p) {
    float2 f;
    asm("mov.b64 {%0, %1}, %2;" : "=f"(f.x), "=f"(f.y) : "l"(p));
    return f;
}

// ---------------------------------------------------------------------------
// Launch 1: h = x @ W (f32x2 FMA, fp16 store).  W (64KB) in shared memory.
// Own launch -> smem reservation doesn't throttle any other work.
// ---------------------------------------------------------------------------
__global__ void k_gemm(const float* __restrict__ x, const float* __restrict__ w) {
    extern __shared__ float ws[];
    for (int i = threadIdx.x; i < GD * GD / 4; i += blockDim.x)
        reinterpret_cast<float4*>(ws)[i] = reinterpret_cast<const float4*>(w)[i];
    __syncthreads();

    const int lane   = threadIdx.x & 31;
    const int warp   = (int)((blockIdx.x * blockDim.x + threadIdx.x) >> 5);
    const int nwarps = (GEMM_BLOCKS * 256) >> 5;
    const ulonglong2* ws2 = reinterpret_cast<const ulonglong2*>(ws);

    for (int row = warp; row < GN; row += nwarps) {
        float xr[4];
#pragma unroll
        for (int j = 0; j < 4; j++) xr[j] = x[(size_t)row * GD + j * 32 + lane];
        uint64_t a01 = 0ull, a23 = 0ull;
#pragma unroll
        for (int j = 0; j < 4; j++) {
#pragma unroll
            for (int kk = 0; kk < 32; kk++) {
                const float xv = __shfl_sync(0xffffffffu, xr[j], kk);
                uint64_t xv2;
                asm("mov.b64 %0, {%1, %1};" : "=l"(xv2) : "f"(xv));
                const ulonglong2 wv = ws2[(j * 32 + kk) * 32 + lane];
                fma2(a01, wv.x, xv2);
                fma2(a23, wv.y, xv2);
            }
        }
        const float2 f01 = unpack_f32x2(a01);
        const float2 f23 = unpack_f32x2(a23);
        const __half2 p = __floats2half2_rn(f01.x, f01.y);
        const __half2 q = __floats2half2_rn(f23.x, f23.y);
        uint2 o;
        o.x = *reinterpret_cast<const unsigned*>(&p);
        o.y = *reinterpret_cast<const unsigned*>(&q);
        reinterpret_cast<uint2*>(g_h)[(size_t)row * 32 + lane] = o;
    }
}

// ---------------------------------------------------------------------------
// Launch 2: bucket scatter, fixed capacity.  gridDim.y = r.  No smem ->
// full occupancy.
// ---------------------------------------------------------------------------
__global__ void k_scatter(const int* __restrict__ rows, const int* __restrict__ cols,
                          const float* __restrict__ vals) {
    const int r = blockIdx.y;
    const int* __restrict__ rr = rows + (size_t)r * GE;
    const int* __restrict__ cc = cols + (size_t)r * GE;
    const float* __restrict__ vv = vals + (size_t)r * GE;

    for (int idx = blockIdx.x * blockDim.x + threadIdx.x; idx < GE;
         idx += SCAT_BLOCKS_X * 256) {
        const int b = r * GN + rr[idx];
        const int pos = atomicAdd(&g_count[b], 1);
        if (pos < CAP) {
            const unsigned short vh = __half_as_ushort(__float2half_rn(vv[idx]));
            g_edges[(size_t)b * CAP + pos] = (unsigned)cc[idx] | ((unsigned)vh << 16);
        }
    }
}

// cvt fp16x2 -> f32x2, then fma.rn.f32x2 into a packed f32x2 accumulator.
__device__ __forceinline__ void cvt_fma(unsigned h2, uint64_t v2, uint64_t& acc) {
    asm("{\n\t"
        ".reg .b16 lo, hi;\n\t"
        ".reg .f32 flo, fhi;\n\t"
        ".reg .b64 g;\n\t"
        "mov.b32 {lo, hi}, %1;\n\t"
        "cvt.f32.f16 flo, lo;\n\t"
        "cvt.f32.f16 fhi, hi;\n\t"
        "mov.b64 g, {flo, fhi};\n\t"
        "fma.rn.f32x2 %0, g, %2, %0;\n\t"
        "}" : "+l"(acc) : "r"(h2), "l"(v2));
}

__device__ __forceinline__ uint64_t rec_v2(unsigned e) {
    float v;
    asm("{\n\t"
        ".reg .b16 lo, hi;\n\t"
        "mov.b32 {lo, hi}, %1;\n\t"
        "cvt.f32.f16 %0, hi;\n\t"
        "}" : "=f"(v) : "r"(e));
    uint64_t v2;
    asm("mov.b64 %0, {%1, %1};" : "=l"(v2) : "f"(v));
    return v2;
}

// ---------------------------------------------------------------------------
// Gather core, 16-edge batches (8 LDG.128 in flight per lane).  pk0 is the
// prefetched first-chunk edge word.  hi = lane>>4 edge parity; q = lane&15.
// ---------------------------------------------------------------------------
__device__ __forceinline__ void seg_core(const uint4* __restrict__ src,
                                         const unsigned* __restrict__ ebase,
                                         int cnt, int hi, int q,
                                         uint64_t acc[4], unsigned pk0) {
    unsigned pk = pk0;
    for (int i = 0; i < cnt; i += 32) {
        const int c = min(32, cnt - i);
        if (i > 0)
            pk = ((threadIdx.x & 31) < c) ? ebase[i + (threadIdx.x & 31)] : 0u;
        int t = 0;
        for (; t + 16 <= c; t += 16) {
            unsigned e[8];
#pragma unroll
            for (int j = 0; j < 8; j++)
                e[j] = __shfl_sync(0xffffffffu, pk, t + 2 * j + hi);
            uint4 g[8];
#pragma unroll
            for (int j = 0; j < 8; j++)
                g[j] = src[(size_t)(e[j] & 0xFFFFu) * 16 + q];
#pragma unroll
            for (int j = 0; j < 8; j++) {
                const uint64_t v = rec_v2(e[j]);
                cvt_fma(g[j].x, v, acc[0]); cvt_fma(g[j].y, v, acc[1]);
                cvt_fma(g[j].z, v, acc[2]); cvt_fma(g[j].w, v, acc[3]);
            }
        }
        for (; t + 8 <= c; t += 8) {
            unsigned e[4];
#pragma unroll
            for (int j = 0; j < 4; j++)
                e[j] = __shfl_sync(0xffffffffu, pk, t + 2 * j + hi);
            uint4 g[4];
#pragma unroll
            for (int j = 0; j < 4; j++)
                g[j] = src[(size_t)(e[j] & 0xFFFFu) * 16 + q];
#pragma unroll
            for (int j = 0; j < 4; j++) {
                const uint64_t v = rec_v2(e[j]);
                cvt_fma(g[j].x, v, acc[0]); cvt_fma(g[j].y, v, acc[1]);
                cvt_fma(g[j].z, v, acc[2]); cvt_fma(g[j].w, v, acc[3]);
            }
        }
        for (; t < c; t += 2) {
            // odd tail: hi=1 half-warp reads a zeroed shfl source -> v=0 no-op
            const unsigned e0 = __shfl_sync(0xffffffffu, pk, t + hi);
            const uint4 g0 = src[(size_t)(e0 & 0xFFFFu) * 16 + q];
            const uint64_t v0 = rec_v2(e0);
            cvt_fma(g0.x, v0, acc[0]); cvt_fma(g0.y, v0, acc[1]);
            cvt_fma(g0.z, v0, acc[2]); cvt_fma(g0.w, v0, acc[3]);
        }
    }
}

__device__ __forceinline__ void half_combine(uint64_t acc[4]) {
#pragma unroll
    for (int k = 0; k < 4; k++) {
        const uint64_t other = __shfl_xor_sync(0xffffffffu, acc[k], 16);
        asm("add.rn.f32x2 %0, %0, %1;" : "+l"(acc[k]) : "l"(other));
    }
}

// ---------------------------------------------------------------------------
// Launch 3: pass 1 (all r): y[b] = filt[b] * sum v * h[col].  Warp per bucket.
// ---------------------------------------------------------------------------
__global__ __launch_bounds__(256) void k_pass1(const float* __restrict__ filt) {
    const int lane = threadIdx.x & 31;
    const int hi   = lane >> 4;
    const int q    = lane & 15;
    const int b    = (blockIdx.x * blockDim.x + threadIdx.x) >> 5;   // NBINS % 8 == 0

    const int cnt = min(g_count[b], CAP);
    const unsigned pk0 = (lane < min(cnt, 32)) ? g_edges[(size_t)b * CAP + lane] : 0u;

    uint64_t acc[4] = {0ull, 0ull, 0ull, 0ull};
    seg_core(reinterpret_cast<const uint4*>(g_h), g_edges + (size_t)b * CAP,
             cnt, hi, q, acc, pk0);
    half_combine(acc);

    if (hi == 0) {
        const float f = __ldg(&filt[b]);
        const float2 a0 = unpack_f32x2(acc[0]);
        const float2 a1 = unpack_f32x2(acc[1]);
        const float2 a2 = unpack_f32x2(acc[2]);
        const float2 a3 = unpack_f32x2(acc[3]);
        const __half2 p0 = __floats2half2_rn(f * a0.x, f * a0.y);
        const __half2 p1 = __floats2half2_rn(f * a1.x, f * a1.y);
        const __half2 p2 = __floats2half2_rn(f * a2.x, f * a2.y);
        const __half2 p3 = __floats2half2_rn(f * a3.x, f * a3.y);
        uint4 o;
        o.x = *reinterpret_cast<const unsigned*>(&p0);
        o.y = *reinterpret_cast<const unsigned*>(&p1);
        o.z = *reinterpret_cast<const unsigned*>(&p2);
        o.w = *reinterpret_cast<const unsigned*>(&p3);
        reinterpret_cast<uint4*>(g_y)[(size_t)b * 16 + q] = o;
    }
}

// ---------------------------------------------------------------------------
// Launch 4 (PROFILED): pass 2, row-per-warp, all 4 segment descriptors
// prefetched.  out[row] = bias + sum_r sum v * y[r][col]; single store;
// re-zeroes counts for the next graph replay.
// ---------------------------------------------------------------------------
__global__ __launch_bounds__(256) void k_pass2(const float* __restrict__ bias,
                                               float* __restrict__ out) {
    const int lane = threadIdx.x & 31;
    const int hi   = lane >> 4;
    const int q    = lane & 15;
    const int row  = (blockIdx.x * blockDim.x + threadIdx.x) >> 5;
    if (row >= GN) return;

    int cnt[GR];
#pragma unroll
    for (int r = 0; r < GR; r++) cnt[r] = min(g_count[r * GN + row], CAP);
    unsigned pk0[GR];
#pragma unroll
    for (int r = 0; r < GR; r++) {
        const size_t eb = (size_t)(r * GN + row) * CAP;
        pk0[r] = (lane < min(cnt[r], 32)) ? g_edges[eb + lane] : 0u;
    }
    if (lane == 0) {
#pragma unroll
        for (int r = 0; r < GR; r++) g_count[r * GN + row] = 0;
    }

    uint64_t acc[4] = {0ull, 0ull, 0ull, 0ull};
#pragma unroll
    for (int r = 0; r < GR; r++) {
        const size_t eb = (size_t)(r * GN + row) * CAP;
        const uint4* y4 = reinterpret_cast<const uint4*>(g_y) + (size_t)r * GN * 16;
        seg_core(y4, g_edges + eb, cnt[r], hi, q, acc, pk0[r]);
    }
    half_combine(acc);

    if (hi == 0) {
        const float2 a0 = unpack_f32x2(acc[0]);
        const float2 a1 = unpack_f32x2(acc[1]);
        const float2 a2 = unpack_f32x2(acc[2]);
        const float2 a3 = unpack_f32x2(acc[3]);
        const float4 b0 = reinterpret_cast<const float4*>(bias)[q * 2];
        const float4 b1 = reinterpret_cast<const float4*>(bias)[q * 2 + 1];
        float4* dst = reinterpret_cast<float4*>(out + (size_t)row * GD + q * 8);
        dst[0] = make_float4(a0.x + b0.x, a0.y + b0.y, a1.x + b0.z, a1.y + b0.w);
        dst[1] = make_float4(a2.x + b1.x, a2.y + b1.y, a3.x + b1.z, a3.y + b1.w);
    }
}

// ---------------------------------------------------------------------------
// Launch. Inputs (metadata order): x, vals, weight, filt, bias, rows, cols.
// ---------------------------------------------------------------------------
extern "C" void kernel_launch(void* const* d_in, const int* in_sizes, int n_in,
                              void* d_out, int out_size) {
    const float* x    = (const float*)d_in[0];
    const float* vals = (const float*)d_in[1];
    const float* w    = (const float*)d_in[2];
    const float* filt = (const float*)d_in[3];
    const float* bias = (const float*)d_in[4];
    const int*   rows = (const int*)d_in[5];
    const int*   cols = (const int*)d_in[6];
    float* out = (float*)d_out;
    (void)in_sizes; (void)n_in; (void)out_size;

    cudaFuncSetAttribute(k_gemm, cudaFuncAttributeMaxDynamicSharedMemorySize,
                         GD * GD * (int)sizeof(float));

    // 1) h = x @ W  (f32x2 FMAs, full-occupancy standalone launch)
    k_gemm<<<GEMM_BLOCKS, 256, GD * GD * sizeof(float)>>>(x, w);

    // 2) bucket scatter (counts zero from BSS / previous replay's pass2)
    dim3 sgrid(SCAT_BLOCKS_X, GR);
    k_scatter<<<sgrid, 256>>>(rows, cols, vals);

    // 3) pass 1
    k_pass1<<<NBINS / 8, 256>>>(filt);

    // 4) pass 2 (+ count re-zero for next replay)
    k_pass2<<<(GN * 32 + 255) / 256, 256>>>(bias, out);
}

// round 17
// speedup vs baseline: 1.0502x; 1.0233x over previous
#include <cuda_runtime.h>
#include <cuda_fp16.h>
#include <cstdint>
#include <cstddef>

#define GN 50000
#define GE 1600000
#define GR 4
#define GD 128
#define NBINS (GR * GN)          // 200000 buckets (r, row)
#define CAP 80                   // bucket capacity; P(Poisson(32) >= 80) ~ 1e-13

#define GEMM_BLOCKS 1024
#define SCAT_BLOCKS_X 512        // x-dim; gridDim.y = GR

// Scratch: device globals (no allocations allowed).
// h, y in fp16; edge record packed to 4B {val:fp16 <<16 | col:u16}.
__device__ __align__(16) __half   g_h[(size_t)GN * GD];          // 12.8 MB
__device__ __align__(16) __half   g_y[(size_t)GR * GN * GD];     // 51.2 MB
__device__ __align__(16) unsigned g_edges[(size_t)NBINS * CAP];  // 64 MB (sparse-touched)
__device__ int g_count[NBINS];   // zero at first use (BSS); re-zeroed by k_pass2

__device__ __forceinline__ void fma2(uint64_t& acc, uint64_t a, uint64_t b) {
    asm("fma.rn.f32x2 %0, %1, %2, %0;" : "+l"(acc) : "l"(a), "l"(b));
}

__device__ __forceinline__ float2 unpack_f32x2(uint64_t p) {
    float2 f;
    asm("mov.b64 {%0, %1}, %2;" : "=f"(f.x), "=f"(f.y) : "l"(p));
    return f;
}

// ---------------------------------------------------------------------------
// h = x @ W (f32x2 FMA, fp16 store).  W (64KB) in shared memory.
// Runs on a side stream, overlapped with the scatter.
// ---------------------------------------------------------------------------
__global__ void k_gemm(const float* __restrict__ x, const float* __restrict__ w) {
    extern __shared__ float ws[];
    for (int i = threadIdx.x; i < GD * GD / 4; i += blockDim.x)
        reinterpret_cast<float4*>(ws)[i] = reinterpret_cast<const float4*>(w)[i];
    __syncthreads();

    const int lane   = threadIdx.x & 31;
    const int warp   = (int)((blockIdx.x * blockDim.x + threadIdx.x) >> 5);
    const int nwarps = (GEMM_BLOCKS * 256) >> 5;
    const ulonglong2* ws2 = reinterpret_cast<const ulonglong2*>(ws);

    for (int row = warp; row < GN; row += nwarps) {
        float xr[4];
#pragma unroll
        for (int j = 0; j < 4; j++) xr[j] = x[(size_t)row * GD + j * 32 + lane];
        uint64_t a01 = 0ull, a23 = 0ull;
#pragma unroll
        for (int j = 0; j < 4; j++) {
#pragma unroll
            for (int kk = 0; kk < 32; kk++) {
                const float xv = __shfl_sync(0xffffffffu, xr[j], kk);
                uint64_t xv2;
                asm("mov.b64 %0, {%1, %1};" : "=l"(xv2) : "f"(xv));
                const ulonglong2 wv = ws2[(j * 32 + kk) * 32 + lane];
                fma2(a01, wv.x, xv2);
                fma2(a23, wv.y, xv2);
            }
        }
        const float2 f01 = unpack_f32x2(a01);
        const float2 f23 = unpack_f32x2(a23);
        const __half2 p = __floats2half2_rn(f01.x, f01.y);
        const __half2 q = __floats2half2_rn(f23.x, f23.y);
        uint2 o;
        o.x = *reinterpret_cast<const unsigned*>(&p);
        o.y = *reinterpret_cast<const unsigned*>(&q);
        reinterpret_cast<uint2*>(g_h)[(size_t)row * 32 + lane] = o;
    }
}

// ---------------------------------------------------------------------------
// Bucket scatter, fixed capacity.  gridDim.y = r.  No smem -> co-schedules
// with the gemm's CTAs on the same SMs.
// ---------------------------------------------------------------------------
__global__ void k_scatter(const int* __restrict__ rows, const int* __restrict__ cols,
                          const float* __restrict__ vals) {
    const int r = blockIdx.y;
    const int* __restrict__ rr = rows + (size_t)r * GE;
    const int* __restrict__ cc = cols + (size_t)r * GE;
    const float* __restrict__ vv = vals + (size_t)r * GE;

    for (int idx = blockIdx.x * blockDim.x + threadIdx.x; idx < GE;
         idx += SCAT_BLOCKS_X * 256) {
        const int b = r * GN + rr[idx];
        const int pos = atomicAdd(&g_count[b], 1);
        if (pos < CAP) {
            const unsigned short vh = __half_as_ushort(__float2half_rn(vv[idx]));
            g_edges[(size_t)b * CAP + pos] = (unsigned)cc[idx] | ((unsigned)vh << 16);
        }
    }
}

// cvt fp16x2 -> f32x2, then fma.rn.f32x2 into a packed f32x2 accumulator.
__device__ __forceinline__ void cvt_fma(unsigned h2, uint64_t v2, uint64_t& acc) {
    asm("{\n\t"
        ".reg .b16 lo, hi;\n\t"
        ".reg .f32 flo, fhi;\n\t"
        ".reg .b64 g;\n\t"
        "mov.b32 {lo, hi}, %1;\n\t"
        "cvt.f32.f16 flo, lo;\n\t"
        "cvt.f32.f16 fhi, hi;\n\t"
        "mov.b64 g, {flo, fhi};\n\t"
        "fma.rn.f32x2 %0, g, %2, %0;\n\t"
        "}" : "+l"(acc) : "r"(h2), "l"(v2));
}

__device__ __forceinline__ uint64_t rec_v2(unsigned e) {
    float v;
    asm("{\n\t"
        ".reg .b16 lo, hi;\n\t"
        "mov.b32 {lo, hi}, %1;\n\t"
        "cvt.f32.f16 %0, hi;\n\t"
        "}" : "=f"(v) : "r"(e));
    uint64_t v2;
    asm("mov.b64 %0, {%1, %1};" : "=l"(v2) : "f"(v));
    return v2;
}

// ---------------------------------------------------------------------------
// Gather core, 16-edge batches (8 LDG.128 in flight per lane).  pk0 is the
// prefetched first-chunk edge word.  hi = lane>>4 edge parity; q = lane&15.
// ---------------------------------------------------------------------------
__device__ __forceinline__ void seg_core(const uint4* __restrict__ src,
                                         const unsigned* __restrict__ ebase,
                                         int cnt, int hi, int q,
                                         uint64_t acc[4], unsigned pk0) {
    unsigned pk = pk0;
    for (int i = 0; i < cnt; i += 32) {
        const int c = min(32, cnt - i);
        if (i > 0)
            pk = ((threadIdx.x & 31) < c) ? ebase[i + (threadIdx.x & 31)] : 0u;
        int t = 0;
        for (; t + 16 <= c; t += 16) {
            unsigned e[8];
#pragma unroll
            for (int j = 0; j < 8; j++)
                e[j] = __shfl_sync(0xffffffffu, pk, t + 2 * j + hi);
            uint4 g[8];
#pragma unroll
            for (int j = 0; j < 8; j++)
                g[j] = src[(size_t)(e[j] & 0xFFFFu) * 16 + q];
#pragma unroll
            for (int j = 0; j < 8; j++) {
                const uint64_t v = rec_v2(e[j]);
                cvt_fma(g[j].x, v, acc[0]); cvt_fma(g[j].y, v, acc[1]);
                cvt_fma(g[j].z, v, acc[2]); cvt_fma(g[j].w, v, acc[3]);
            }
        }
        for (; t + 8 <= c; t += 8) {
            unsigned e[4];
#pragma unroll
            for (int j = 0; j < 4; j++)
                e[j] = __shfl_sync(0xffffffffu, pk, t + 2 * j + hi);
            uint4 g[4];
#pragma unroll
            for (int j = 0; j < 4; j++)
                g[j] = src[(size_t)(e[j] & 0xFFFFu) * 16 + q];
#pragma unroll
            for (int j = 0; j < 4; j++) {
                const uint64_t v = rec_v2(e[j]);
                cvt_fma(g[j].x, v, acc[0]); cvt_fma(g[j].y, v, acc[1]);
                cvt_fma(g[j].z, v, acc[2]); cvt_fma(g[j].w, v, acc[3]);
            }
        }
        for (; t < c; t += 2) {
            // odd tail: hi=1 half-warp reads a zeroed shfl source -> v=0 no-op
            const unsigned e0 = __shfl_sync(0xffffffffu, pk, t + hi);
            const uint4 g0 = src[(size_t)(e0 & 0xFFFFu) * 16 + q];
            const uint64_t v0 = rec_v2(e0);
            cvt_fma(g0.x, v0, acc[0]); cvt_fma(g0.y, v0, acc[1]);
            cvt_fma(g0.z, v0, acc[2]); cvt_fma(g0.w, v0, acc[3]);
        }
    }
}

__device__ __forceinline__ void half_combine(uint64_t acc[4]) {
#pragma unroll
    for (int k = 0; k < 4; k++) {
        const uint64_t other = __shfl_xor_sync(0xffffffffu, acc[k], 16);
        asm("add.rn.f32x2 %0, %0, %1;" : "+l"(acc[k]) : "l"(other));
    }
}

// ---------------------------------------------------------------------------
// Pass 1 (all r): y[b] = filt[b] * sum v * h[col].  Warp per bucket.
// ---------------------------------------------------------------------------
__global__ __launch_bounds__(256) void k_pass1(const float* __restrict__ filt) {
    const int lane = threadIdx.x & 31;
    const int hi   = lane >> 4;
    const int q    = lane & 15;
    const int b    = (blockIdx.x * blockDim.x + threadIdx.x) >> 5;   // NBINS % 8 == 0

    const int cnt = min(g_count[b], CAP);
    const unsigned pk0 = (lane < min(cnt, 32)) ? g_edges[(size_t)b * CAP + lane] : 0u;

    uint64_t acc[4] = {0ull, 0ull, 0ull, 0ull};
    seg_core(reinterpret_cast<const uint4*>(g_h), g_edges + (size_t)b * CAP,
             cnt, hi, q, acc, pk0);
    half_combine(acc);

    if (hi == 0) {
        const float f = __ldg(&filt[b]);
        const float2 a0 = unpack_f32x2(acc[0]);
        const float2 a1 = unpack_f32x2(acc[1]);
        const float2 a2 = unpack_f32x2(acc[2]);
        const float2 a3 = unpack_f32x2(acc[3]);
        const __half2 p0 = __floats2half2_rn(f * a0.x, f * a0.y);
        const __half2 p1 = __floats2half2_rn(f * a1.x, f * a1.y);
        const __half2 p2 = __floats2half2_rn(f * a2.x, f * a2.y);
        const __half2 p3 = __floats2half2_rn(f * a3.x, f * a3.y);
        uint4 o;
        o.x = *reinterpret_cast<const unsigned*>(&p0);
        o.y = *reinterpret_cast<const unsigned*>(&p1);
        o.z = *reinterpret_cast<const unsigned*>(&p2);
        o.w = *reinterpret_cast<const unsigned*>(&p3);
        reinterpret_cast<uint4*>(g_y)[(size_t)b * 16 + q] = o;
    }
}

// ---------------------------------------------------------------------------
// Pass 2, row-per-warp, all 4 segment descriptors prefetched.
// out[row] = bias + sum_r sum v * y[r][col]; single store; re-zeroes counts.
// ---------------------------------------------------------------------------
__global__ __launch_bounds__(256) void k_pass2(const float* __restrict__ bias,
                                               float* __restrict__ out) {
    const int lane = threadIdx.x & 31;
    const int hi   = lane >> 4;
    const int q    = lane & 15;
    const int row  = (blockIdx.x * blockDim.x + threadIdx.x) >> 5;
    if (row >= GN) return;

    int cnt[GR];
#pragma unroll
    for (int r = 0; r < GR; r++) cnt[r] = min(g_count[r * GN + row], CAP);
    unsigned pk0[GR];
#pragma unroll
    for (int r = 0; r < GR; r++) {
        const size_t eb = (size_t)(r * GN + row) * CAP;
        pk0[r] = (lane < min(cnt[r], 32)) ? g_edges[eb + lane] : 0u;
    }
    if (lane == 0) {
#pragma unroll
        for (int r = 0; r < GR; r++) g_count[r * GN + row] = 0;
    }

    uint64_t acc[4] = {0ull, 0ull, 0ull, 0ull};
#pragma unroll
    for (int r = 0; r < GR; r++) {
        const size_t eb = (size_t)(r * GN + row) * CAP;
        const uint4* y4 = reinterpret_cast<const uint4*>(g_y) + (size_t)r * GN * 16;
        seg_core(y4, g_edges + eb, cnt[r], hi, q, acc, pk0[r]);
    }
    half_combine(acc);

    if (hi == 0) {
        const float2 a0 = unpack_f32x2(acc[0]);
        const float2 a1 = unpack_f32x2(acc[1]);
        const float2 a2 = unpack_f32x2(acc[2]);
        const float2 a3 = unpack_f32x2(acc[3]);
        const float4 b0 = reinterpret_cast<const float4*>(bias)[q * 2];
        const float4 b1 = reinterpret_cast<const float4*>(bias)[q * 2 + 1];
        float4* dst = reinterpret_cast<float4*>(out + (size_t)row * GD + q * 8);
        dst[0] = make_float4(a0.x + b0.x, a0.y + b0.y, a1.x + b0.z, a1.y + b0.w);
        dst[1] = make_float4(a2.x + b1.x, a2.y + b1.y, a3.x + b1.z, a3.y + b1.w);
    }
}

// ---------------------------------------------------------------------------
// Launch. Inputs (metadata order): x, vals, weight, filt, bias, rows, cols.
// gemm (side stream) and scatter (main stream) overlap; events fork/join the
// capture graph.  Streams/events created once in static init (host-side only).
// ---------------------------------------------------------------------------
extern "C" void kernel_launch(void* const* d_in, const int* in_sizes, int n_in,
                              void* d_out, int out_size) {
    const float* x    = (const float*)d_in[0];
    const float* vals = (const float*)d_in[1];
    const float* w    = (const float*)d_in[2];
    const float* filt = (const float*)d_in[3];
    const float* bias = (const float*)d_in[4];
    const int*   rows = (const int*)d_in[5];
    const int*   cols = (const int*)d_in[6];
    float* out = (float*)d_out;
    (void)in_sizes; (void)n_in; (void)out_size;

    static cudaStream_t s2 = nullptr;
    static cudaEvent_t evFork = nullptr, evJoin = nullptr;
    if (!s2) {
        cudaStreamCreateWithFlags(&s2, cudaStreamNonBlocking);
        cudaEventCreateWithFlags(&evFork, cudaEventDisableTiming);
        cudaEventCreateWithFlags(&evJoin, cudaEventDisableTiming);
        cudaFuncSetAttribute(k_gemm, cudaFuncAttributeMaxDynamicSharedMemorySize,
                             GD * GD * (int)sizeof(float));
    }

    // fork: gemm on s2, scatter on the main (captured) stream
    cudaEventRecord(evFork, 0);
    cudaStreamWaitEvent(s2, evFork, 0);
    k_gemm<<<GEMM_BLOCKS, 256, GD * GD * sizeof(float), s2>>>(x, w);
    cudaEventRecord(evJoin, s2);

    dim3 sgrid(SCAT_BLOCKS_X, GR);
    k_scatter<<<sgrid, 256>>>(rows, cols, vals);

    // join: pass1 needs both h and the buckets
    cudaStreamWaitEvent(0, evJoin, 0);

    // pass 1
    k_pass1<<<NBINS / 8, 256>>>(filt);

    // pass 2 (+ count re-zero for next replay)
    k_pass2<<<(GN * 32 + 255) / 256, 256>>>(bias, out);
}